// round 13
// baseline (speedup 1.0000x reference)
#include <cuda_runtime.h>
#include <cuda_bf16.h>
#include <mma.h>
#include <cstdint>

using namespace nvcuda;

// ============================================================================
// Grouped GEMM (MoE ragged splits), GB300.
//
// SOLVED (R8-R12 measurement campaign): the harness materializes ALL tensors
// as float32 (numpy has no bf16; jax bf16 arrays are upcast — low 16 mantissa
// bits are zero). in_sizes/out_size are fp32 element counts. Reference output
// is the bf16 matmul result upcast to fp32.
//
//   out[r,:] = bf16round( x[r,:] @ w[g(r)] ),  IN=256, OUT=128 (fp32 I/O)
//   splits all % 128 == 0  ->  one expert per 128-row tile
//
// Kernel: 1 CTA per 128x128 tile (6144 CTAs), 256 thr = 8 warps (4M x 2N),
// warp tile 32x64 = 2x4 tf32 wmma m16n16k8 frags (tf32 mantissa 10 bits >=
// bf16's 8 -> exact products; fp32 accum matches XLA). K=256 in 8 chunks of
// 32, 4-stage cp.async ring (138KB smem). Epilogue: round acc to bf16,
// store_matrix_sync direct to global fp32.
// ============================================================================

#define A_PITCH_F 36                    // fp32 per smem A row (144 B)
#define B_PITCH_F 132                   // fp32 per smem B row (528 B)
#define SA_BYTES  (128u * 144u)         // 18432
#define SB_BYTES  (32u * 528u)          // 16896
#define STAGE     (SA_BYTES + SB_BYTES) // 35328
#define NSTAGE    4u
#define SMEM_BYTES (NSTAGE * STAGE)     // 141312

// ---------------------------------------------------------------- helpers ---
static __device__ __forceinline__ uint32_t smem_u32(const void* p) {
    uint32_t a;
    asm("{ .reg .u64 t; cvta.to.shared.u64 t, %1; cvt.u32.u64 %0, t; }"
        : "=r"(a) : "l"(p));
    return a;
}
static __device__ __forceinline__ void cp16(uint32_t dst, const void* src) {
    asm volatile("cp.async.cg.shared.global [%0], [%1], 16;"
                 :: "r"(dst), "l"(src) : "memory");
}
static __device__ __forceinline__ void cp_commit() {
    asm volatile("cp.async.commit_group;" ::: "memory");
}
#define CP_WAIT(n) asm volatile("cp.async.wait_group %0;" :: "n"(n) : "memory")

// ------------------------------------------------------------- stage loads ---
// A chunk: x tile rows [0,128) x k [kc*32, kc*32+32) fp32.
// B chunk: w[g] rows k [kc*32, kc*32+32) x n [0,128) fp32.
static __device__ __forceinline__ void load_chunk(
    const float* __restrict__ xb, const float* __restrict__ wb,
    int kc, uint32_t stage_base, int tid) {
    uint32_t sA = stage_base;
    uint32_t sB = stage_base + SA_BYTES;
#pragma unroll
    for (int j = 0; j < 4; ++j) {
        int idx = tid + j * 256;                 // 0..1023
        int ra = idx >> 3, ca = idx & 7;         // A: 128 rows x 8 16B-chunks
        cp16(sA + (uint32_t)ra * 144u + (uint32_t)(ca << 4),
             xb + (size_t)ra * 256 + kc * 32 + ca * 4);
        int rb = idx >> 5, cb = idx & 31;        // B: 32 rows x 32 16B-chunks
        cp16(sB + (uint32_t)rb * 528u + (uint32_t)(cb << 4),
             wb + (size_t)(kc * 32 + rb) * 128 + cb * 4);
    }
    cp_commit();
}

// --------------------------------------------------------------- compute ----
using FragA = wmma::fragment<wmma::matrix_a, 16, 16, 8,
                             wmma::precision::tf32, wmma::row_major>;
using FragB = wmma::fragment<wmma::matrix_b, 16, 16, 8,
                             wmma::precision::tf32, wmma::row_major>;
using FragC = wmma::fragment<wmma::accumulator, 16, 16, 8, float>;

static __device__ __forceinline__ void compute_chunk(
    const char* st, FragC cfr[2][4], int wm, int wn) {
    const float* sA = (const float*)st;
    const float* sB = (const float*)(st + SA_BYTES);
#pragma unroll
    for (int ks = 0; ks < 4; ++ks) {
        int kk = ks * 8;
        FragA a[2];
#pragma unroll
        for (int m = 0; m < 2; ++m) {
            wmma::load_matrix_sync(a[m],
                sA + (size_t)(wm + m * 16) * A_PITCH_F + kk, A_PITCH_F);
#pragma unroll
            for (int t = 0; t < a[m].num_elements; ++t)
                a[m].x[t] = wmma::__float_to_tf32(a[m].x[t]);
        }
#pragma unroll
        for (int n = 0; n < 4; ++n) {
            FragB b;
            wmma::load_matrix_sync(b,
                sB + (size_t)kk * B_PITCH_F + wn + n * 16, B_PITCH_F);
#pragma unroll
            for (int t = 0; t < b.num_elements; ++t)
                b.x[t] = wmma::__float_to_tf32(b.x[t]);
#pragma unroll
            for (int m = 0; m < 2; ++m)
                wmma::mma_sync(cfr[m][n], a[m], b, cfr[m][n]);
        }
    }
}

// ----------------------------------------------------------------- kernel ---
__global__ void __launch_bounds__(256, 1) gg_kernel(
    const float* __restrict__ x,
    const float* __restrict__ w,
    const int* __restrict__ gsizes,
    float* __restrict__ out,
    int n_groups) {
    extern __shared__ char smem[];
    int tid = threadIdx.x;
    int wid = tid >> 5;
    int tile = blockIdx.x;

    // expert owning this tile (splits % 128 == 0 -> exact tile boundaries)
    int g = n_groups - 1;
    {
        int acc = 0;
        for (int i = 0; i < n_groups; ++i) {
            acc += gsizes[i] >> 7;
            if (tile < acc) { g = i; break; }
        }
    }

    const float* xb = x + (size_t)tile * 128 * 256;
    const float* wb = w + (size_t)g * 256 * 128;
    uint32_t sb = smem_u32(smem);

    // prologue: fill 3 of the 4 ring stages (chunks 0..2)
    load_chunk(xb, wb, 0, sb + 0 * STAGE, tid);
    load_chunk(xb, wb, 1, sb + 1 * STAGE, tid);
    load_chunk(xb, wb, 2, sb + 2 * STAGE, tid);

    int wm = (wid & 3) << 5;          // warp M offset: 0/32/64/96
    int wn = (wid >> 2) << 6;         // warp N offset: 0/64

    FragC cfr[2][4];
#pragma unroll
    for (int m = 0; m < 2; ++m)
#pragma unroll
        for (int n = 0; n < 4; ++n)
            wmma::fill_fragment(cfr[m][n], 0.0f);

#pragma unroll
    for (int i = 0; i < 8; ++i) {
        if (i + 3 < 8)
            load_chunk(xb, wb, i + 3, sb + (uint32_t)((i + 3) & 3) * STAGE, tid);
        // wait until chunk i's group has landed
        if (i < 5)      CP_WAIT(3);
        else if (i == 5) CP_WAIT(2);
        else if (i == 6) CP_WAIT(1);
        else             CP_WAIT(0);
        __syncthreads();
        compute_chunk(smem + (size_t)(i & 3) * STAGE, cfr, wm, wn);
        __syncthreads();   // stage (i&3) free for reuse by iteration i+4's load
    }

    // epilogue: round to bf16 (reference is bf16-rounded), store fp32 direct
    float* ob = out + (size_t)tile * 128 * 128;
#pragma unroll
    for (int m = 0; m < 2; ++m)
#pragma unroll
        for (int n = 0; n < 4; ++n) {
#pragma unroll
            for (int t = 0; t < cfr[m][n].num_elements; ++t)
                cfr[m][n].x[t] =
                    __bfloat162float(__float2bfloat16(cfr[m][n].x[t]));
            wmma::store_matrix_sync(
                ob + (size_t)(wm + m * 16) * 128 + wn + n * 16,
                cfr[m][n], 128, wmma::mem_row_major);
        }
}

// -------------------------------------------------------------------- host ---
extern "C" void kernel_launch(void* const* d_in, const int* in_sizes, int n_in,
                              void* d_out, int out_size) {
    // identify inputs by element count (x=max, group_sizes=min, w=rest)
    int ix = 0, ig = 0;
    for (int i = 1; i < n_in; ++i) {
        if (in_sizes[i] > in_sizes[ix]) ix = i;
        if (in_sizes[i] < in_sizes[ig]) ig = i;
    }
    int iw = 0;
    for (int i = 0; i < n_in; ++i)
        if (i != ix && i != ig) { iw = i; break; }

    const float* x  = (const float*)d_in[ix];      // fp32 (bf16-upcast values)
    const float* w  = (const float*)d_in[iw];      // fp32 (bf16-upcast values)
    const int*   gs = (const int*)d_in[ig];
    float*      out = (float*)d_out;               // fp32 output

    int n_groups = in_sizes[ig];
    if (n_groups > 64) n_groups = 64;
    int n_tiles = in_sizes[ix] / (256 * 128);

    cudaFuncSetAttribute(gg_kernel, cudaFuncAttributeMaxDynamicSharedMemorySize,
                         (int)SMEM_BYTES);
    gg_kernel<<<n_tiles, 256, SMEM_BYTES>>>(x, w, gs, out, n_groups);
}